// round 11
// baseline (speedup 1.0000x reference)
#include <cuda_runtime.h>
#include <cuda_bf16.h>
#include <cstdint>

// Embedding_78666620994160
// out[t, e] = (W[e, ids[t]] + b[e]) * sqrt(512)
// ids: [8*4096] int32, W: [512, 50257] f32, b: [512] f32 -> out [32768,512] f32
//
// v10: K1 = fused sort (blocks 0-63: hist -> 64-block barrier -> local scan ->
// scatter) PLUS L2 prefetch of W on blocks 64-591 (otherwise-idle SMs pull
// the non-resident part of W into L2 during the sort window).
// K2 = transposed gather (proven config) now reads W mostly from L2.
// All sync state epoch-monotonic => graph-replay safe.

#define VOCAB    50257
#define EMB      512
#define N_TOKENS (8 * 4096)
#define BUCKET_SHIFT 5
#define NBINS_PAD 2048

#define SORT_BLOCKS 64
#define K1_BLOCKS   592              // 148 SMs x occ 4, one full wave
#define NF4         ((EMB * VOCAB) / 4)   // 6,432,896 float4 in W

#define TOK_PER_BLK 32
#define E4_PER_BLK  64
#define S4_PITCH    65

__device__ int  g_hist[NBINS_PAD];   // zeroed at load; gather re-zeroes each launch
__device__ int  g_cnt[NBINS_PAD];    // monotonic per-bucket scatter counters
__device__ int2 g_sorted[N_TOKENS];  // (token, id) bucket-sorted
__device__ int  g_epoch = 0;         // completed launches; gather increments
__device__ volatile int g_bar = 0;   // monotonic barrier counter

// ---- K1: sort (blocks 0-63) + W L2-prefetch (blocks 64-591) ----
__global__ void __launch_bounds__(512, 4)
sort_prefetch_kernel(const int* __restrict__ ids,
                     const float* __restrict__ W)
{
    __shared__ int sb[NBINS_PAD];
    __shared__ int wsum[16];

    const int tid = threadIdx.x;

    if (blockIdx.x >= SORT_BLOCKS) {
        // -------- prefetch W into L2 (ld.global.cg, results discarded) --------
        const int nthr   = (K1_BLOCKS - SORT_BLOCKS) * 512;        // 270336
        int       i      = (blockIdx.x - SORT_BLOCKS) * 512 + tid;
        const float4* Wp = (const float4*)W;
        for (; i < NF4; i += nthr) {
            float a, bq, c, d;
            asm volatile("ld.global.cg.v4.f32 {%0,%1,%2,%3}, [%4];"
                         : "=f"(a), "=f"(bq), "=f"(c), "=f"(d)
                         : "l"(Wp + i));
        }
        return;
    }

    // -------- sort path (blocks 0-63) --------
    const int lane = tid & 31, wid = tid >> 5;
    const int e0   = g_epoch;               // stable (only gather modifies it)

    // Phase A: histogram (1 token/thread, device-scope atomic -> L2)
    const int t  = blockIdx.x * 512 + tid;
    const int id = __ldg(&ids[t]);
    atomicAdd(&g_hist[id >> BUCKET_SHIFT], 1);

    // 64-block grid barrier (sort blocks only; all co-resident)
    __threadfence();
    __syncthreads();
    if (tid == 0) {
        atomicAdd((int*)&g_bar, 1);
        const int target = e0 * SORT_BLOCKS + SORT_BLOCKS;
        while (g_bar < target) __nanosleep(32);
    }
    __syncthreads();
    __threadfence();

    // Phase B: local scan of 2048 bins (4/thread), redundant per block
    const int base = tid * 4;
    int v0 = g_hist[base + 0];
    int v1 = g_hist[base + 1];
    int v2 = g_hist[base + 2];
    int v3 = g_hist[base + 3];
    int s  = v0 + v1 + v2 + v3;

    int x = s;
    #pragma unroll
    for (int off = 1; off < 32; off <<= 1) {
        int y = __shfl_up_sync(0xffffffffu, x, off);
        if (lane >= off) x += y;
    }
    if (lane == 31) wsum[wid] = x;
    __syncthreads();
    if (wid == 0 && lane < 16) {
        int w = wsum[lane];
        int xw = w;
        #pragma unroll
        for (int off = 1; off < 16; off <<= 1) {
            int y = __shfl_up_sync(0x0000ffffu, xw, off);
            if (lane >= off) xw += y;
        }
        wsum[lane] = xw - w;                 // exclusive warp base
    }
    __syncthreads();

    int run = wsum[wid] + (x - s);           // exclusive prefix of bin 'base'
    // bases adjusted for monotonic counters: g_cnt[b] == e0*count[b] at entry
    sb[base + 0] = run - e0 * v0;   run += v0;
    sb[base + 1] = run - e0 * v1;   run += v1;
    sb[base + 2] = run - e0 * v2;   run += v2;
    sb[base + 3] = run - e0 * v3;
    __syncthreads();

    // Phase C: scatter this block's 512 tokens
    int bkt = id >> BUCKET_SHIFT;
    int pos = sb[bkt] + atomicAdd(&g_cnt[bkt], 1);
    __stcs(&g_sorted[pos], make_int2(t, id));
}

// ---- K2: transposed gather (proven config) + housekeeping ----
// Block tile: 32 sorted tokens x 64 float4. blockDim=(32,16).
// Phase 1: lane = token -> warp gather hits few 32B sectors (sorted ids),
//          W now mostly L2-resident thanks to the prefetch.
// Phase 2: coalesced float4 streaming stores, token-major.
__global__ void __launch_bounds__(512, 4)
emb_gather_tr_kernel(const float* __restrict__ W,
                     const float* __restrict__ b,
                     float* __restrict__ out)
{
    const float SCALE = 22.62741699796952f; // sqrt(512)
    __shared__ float4 S4[TOK_PER_BLK * S4_PITCH];

    // housekeeping: block (0,0) zeroes hist (already consumed) and bumps epoch
    if (blockIdx.x == 0 && blockIdx.y == 0) {
        int tid = threadIdx.y * 32 + threadIdx.x;
        int i4 = tid * 4;
        g_hist[i4 + 0] = 0;
        g_hist[i4 + 1] = 0;
        g_hist[i4 + 2] = 0;
        g_hist[i4 + 3] = 0;
        if (tid == 0) g_epoch += 1;
    }

    int t  = threadIdx.x;                        // 0..31 local token
    int ty = threadIdx.y;                        // 0..15
    int s  = blockIdx.x * TOK_PER_BLK + t;       // sorted position
    int e4base = blockIdx.y * E4_PER_BLK;        // global float4 offset

    int id = __ldg(&g_sorted[s]).y;

    // Phase 1: gather 4 e4-slots per thread
    #pragma unroll
    for (int i = 0; i < 4; i++) {
        int e4l = ty + 16 * i;                   // 0..63 local
        int e4g = e4base + e4l;
        float4 bv = __ldg((const float4*)b + e4g);
        const float* wp = W + (size_t)(4 * e4g) * VOCAB + id;
        float4 r;
        r.x = (__ldg(wp)                      + bv.x) * SCALE;
        r.y = (__ldg(wp + (size_t)VOCAB)      + bv.y) * SCALE;
        r.z = (__ldg(wp + (size_t)2 * VOCAB)  + bv.z) * SCALE;
        r.w = (__ldg(wp + (size_t)3 * VOCAB)  + bv.w) * SCALE;
        S4[t * S4_PITCH + e4l] = r;
    }

    __syncthreads();

    // Phase 2: token-major coalesced float4 streaming stores
    int tid  = ty * 32 + t;                      // 0..511
    int tl   = tid >> 4;                         // 0..31 local token
    int ey   = tid & 15;                         // 0..15
    int token = __ldg(&g_sorted[blockIdx.x * TOK_PER_BLK + tl]).x;
    float4* outp = (float4*)out + (size_t)token * (EMB / 4) + e4base;
    #pragma unroll
    for (int i = 0; i < 4; i++) {
        int e4l = ey + 16 * i;
        __stcs(&outp[e4l], S4[tl * S4_PITCH + e4l]);
    }
}

extern "C" void kernel_launch(void* const* d_in, const int* in_sizes, int n_in,
                              void* d_out, int out_size)
{
    const int*   ids = (const int*)d_in[0];    // [32768] int32
    const float* W   = (const float*)d_in[1];  // [512*50257]
    const float* b   = (const float*)d_in[2];  // [512]
    float*       out = (float*)d_out;          // [32768*512]

    sort_prefetch_kernel<<<K1_BLOCKS, 512>>>(ids, W);

    dim3 block(32, 16, 1);
    dim3 grid(N_TOKENS / TOK_PER_BLK, EMB / (4 * E4_PER_BLK), 1);  // 1024 x 2
    emb_gather_tr_kernel<<<grid, block>>>(W, b, out);
}

// round 12
// speedup vs baseline: 1.0533x; 1.0533x over previous
#include <cuda_runtime.h>
#include <cuda_bf16.h>
#include <cstdint>

// Embedding_78666620994160
// out[t, e] = (W[e, ids[t]] + b[e]) * sqrt(512)
// ids: [8*4096] int32, W: [512, 50257] f32, b: [512] f32 -> out [32768,512] f32
//
// v11 = v9 (best: 41.4us) + L2 evict_last policy on W loads in the gather.
// W (103MB) fits L2 (126MB); evict_last lets it survive the streaming output
// writes (__stcs = evict_first) across graph replays -> gather DRAM reads
// collapse to near zero in steady state.

#define VOCAB    50257
#define EMB      512
#define N_TOKENS (8 * 4096)
#define BUCKET_SHIFT 5
#define NBINS_PAD 2048

#define SORT_BLOCKS 64
#define TOK_PER_BLK 32
#define E4_PER_BLK  64
#define S4_PITCH    65

__device__ int  g_hist[NBINS_PAD];   // zeroed at load; gather re-zeroes each launch
__device__ int  g_cnt[NBINS_PAD];    // monotonic per-bucket scatter counters
__device__ int2 g_sorted[N_TOKENS];  // (token, id) bucket-sorted
__device__ int  g_epoch = 0;         // completed launches; gather increments
__device__ volatile int g_bar = 0;   // monotonic barrier counter

// W load with L2 evict_last hint (keeps W resident across replays)
__device__ __forceinline__ float ldg_keep(const float* p, uint64_t pol)
{
    float v;
    asm("ld.global.nc.L2::cache_hint.f32 %0, [%1], %2;"
        : "=f"(v) : "l"(p), "l"(pol));
    return v;
}

// ---- K1: fused hist + barrier + local scan + scatter (64 blocks x 512) ----
__global__ void __launch_bounds__(512, 2)
sort_kernel(const int* __restrict__ ids)
{
    __shared__ int sb[NBINS_PAD];
    __shared__ int wsum[16];

    const int tid  = threadIdx.x;
    const int lane = tid & 31, wid = tid >> 5;
    const int e0   = g_epoch;               // stable (only gather modifies it)

    // Phase A: histogram (1 token/thread, device-scope atomic -> L2)
    const int t  = blockIdx.x * 512 + tid;
    const int id = __ldg(&ids[t]);
    atomicAdd(&g_hist[id >> BUCKET_SHIFT], 1);

    // 64-block grid barrier (all blocks co-resident: 64 << 148 SMs)
    __threadfence();
    __syncthreads();
    if (tid == 0) {
        atomicAdd((int*)&g_bar, 1);
        const int target = e0 * SORT_BLOCKS + SORT_BLOCKS;
        while (g_bar < target) __nanosleep(32);
    }
    __syncthreads();
    __threadfence();

    // Phase B: local scan of 2048 bins (4/thread), redundant per block
    const int base = tid * 4;
    int v0 = g_hist[base + 0];
    int v1 = g_hist[base + 1];
    int v2 = g_hist[base + 2];
    int v3 = g_hist[base + 3];
    int s  = v0 + v1 + v2 + v3;

    int x = s;
    #pragma unroll
    for (int off = 1; off < 32; off <<= 1) {
        int y = __shfl_up_sync(0xffffffffu, x, off);
        if (lane >= off) x += y;
    }
    if (lane == 31) wsum[wid] = x;
    __syncthreads();
    if (wid == 0 && lane < 16) {
        int w = wsum[lane];
        int xw = w;
        #pragma unroll
        for (int off = 1; off < 16; off <<= 1) {
            int y = __shfl_up_sync(0x0000ffffu, xw, off);
            if (lane >= off) xw += y;
        }
        wsum[lane] = xw - w;                 // exclusive warp base
    }
    __syncthreads();

    int run = wsum[wid] + (x - s);           // exclusive prefix of bin 'base'
    // bases adjusted for monotonic counters: g_cnt[b] == e0*count[b] at entry
    sb[base + 0] = run - e0 * v0;   run += v0;
    sb[base + 1] = run - e0 * v1;   run += v1;
    sb[base + 2] = run - e0 * v2;   run += v2;
    sb[base + 3] = run - e0 * v3;
    __syncthreads();

    // Phase C: scatter this block's 512 tokens
    int bkt = id >> BUCKET_SHIFT;
    int pos = sb[bkt] + atomicAdd(&g_cnt[bkt], 1);
    __stcs(&g_sorted[pos], make_int2(t, id));
}

// ---- K2: transposed gather + housekeeping ----
// Block tile: 32 sorted tokens x 64 float4. blockDim=(32,16).
// Phase 1: lane = token -> warp gather hits few 32B sectors (sorted ids);
//          W loads carry L2::evict_last so W stays resident across replays.
// Phase 2: coalesced float4 streaming stores (evict_first), token-major.
__global__ void __launch_bounds__(512, 4)
emb_gather_tr_kernel(const float* __restrict__ W,
                     const float* __restrict__ b,
                     float* __restrict__ out)
{
    const float SCALE = 22.62741699796952f; // sqrt(512)
    __shared__ float4 S4[TOK_PER_BLK * S4_PITCH];

    // housekeeping: block (0,0) zeroes hist (already consumed) and bumps epoch
    if (blockIdx.x == 0 && blockIdx.y == 0) {
        int tid = threadIdx.y * 32 + threadIdx.x;
        int i4 = tid * 4;
        g_hist[i4 + 0] = 0;
        g_hist[i4 + 1] = 0;
        g_hist[i4 + 2] = 0;
        g_hist[i4 + 3] = 0;
        if (tid == 0) g_epoch += 1;
    }

    uint64_t pol;
    asm("createpolicy.fractional.L2::evict_last.b64 %0, 1.0;" : "=l"(pol));

    int t  = threadIdx.x;                        // 0..31 local token
    int ty = threadIdx.y;                        // 0..15
    int s  = blockIdx.x * TOK_PER_BLK + t;       // sorted position
    int e4base = blockIdx.y * E4_PER_BLK;        // global float4 offset

    int id = __ldg(&g_sorted[s]).y;

    // Phase 1: gather 4 e4-slots per thread
    #pragma unroll
    for (int i = 0; i < 4; i++) {
        int e4l = ty + 16 * i;                   // 0..63 local
        int e4g = e4base + e4l;
        float4 bv = __ldg((const float4*)b + e4g);
        const float* wp = W + (size_t)(4 * e4g) * VOCAB + id;
        float4 r;
        r.x = (ldg_keep(wp,                     pol) + bv.x) * SCALE;
        r.y = (ldg_keep(wp + (size_t)VOCAB,     pol) + bv.y) * SCALE;
        r.z = (ldg_keep(wp + (size_t)2 * VOCAB, pol) + bv.z) * SCALE;
        r.w = (ldg_keep(wp + (size_t)3 * VOCAB, pol) + bv.w) * SCALE;
        S4[t * S4_PITCH + e4l] = r;
    }

    __syncthreads();

    // Phase 2: token-major coalesced float4 streaming stores
    int tid  = ty * 32 + t;                      // 0..511
    int tl   = tid >> 4;                         // 0..31 local token
    int ey   = tid & 15;                         // 0..15
    int token = __ldg(&g_sorted[blockIdx.x * TOK_PER_BLK + tl]).x;
    float4* outp = (float4*)out + (size_t)token * (EMB / 4) + e4base;
    #pragma unroll
    for (int i = 0; i < 4; i++) {
        int e4l = ey + 16 * i;
        __stcs(&outp[e4l], S4[tl * S4_PITCH + e4l]);
    }
}

extern "C" void kernel_launch(void* const* d_in, const int* in_sizes, int n_in,
                              void* d_out, int out_size)
{
    const int*   ids = (const int*)d_in[0];    // [32768] int32
    const float* W   = (const float*)d_in[1];  // [512*50257]
    const float* b   = (const float*)d_in[2];  // [512]
    float*       out = (float*)d_out;          // [32768*512]

    sort_kernel<<<SORT_BLOCKS, 512>>>(ids);

    dim3 block(32, 16, 1);
    dim3 grid(N_TOKENS / TOK_PER_BLK, EMB / (4 * E4_PER_BLK), 1);  // 1024 x 2
    emb_gather_tr_kernel<<<grid, block>>>(W, b, out);
}